// round 10
// baseline (speedup 1.0000x reference)
#include <cuda_runtime.h>

namespace {
constexpr int T_STEPS = 1000;
constexpr int B       = 256;
constexpr int IN_DIM  = 3;
constexpr int H       = 512;
constexpr int OUT_DIM = 2;
constexpr int NT      = 512;          // one thread per neuron
constexpr int NWARP   = NT / 32;      // 16
constexpr int TAIL    = 10;           // readout window
constexpr int T_HALF  = 500;          // T split point
// half 0 stores t in [0,500): 10 chunks of 50
// half 1 stores t in [500,990): 10 chunks of 49, then 10 tail steps
constexpr int CH0 = 50;
constexpr int CH1 = 49;
static_assert(T_HALF % CH0 == 0, "half0 chunks");
static_assert((T_STEPS - TAIL - T_HALF) % CH1 == 0, "half1 chunks");
}

__device__ __forceinline__ void snn_step(float xv0, float xv1, float xv2,
                                         float w10, float w11, float w12,
                                         float& mem, bool& p, float& s)
{
    // cur = x0*w0 (+fma) x1*w1 (+fma) x2*w2  (k-ascending fma chain)
    float cur = __fmaf_rn(xv2, w12, __fmaf_rn(xv1, w11, __fmul_rn(xv0, w10)));
    // mem_new = (0.8*mem + cur) * (1 - reset), reset from PREVIOUS mem (== prev spike)
    float vm = __fadd_rn(__fmul_rn(0.8f, mem), cur);
    float mn = p ? 0.0f : vm;
    p   = (mn > 1.0f);
    mem = mn;
    s   = p ? 1.0f : 0.0f;
}

__global__ __launch_bounds__(NT)
void snn_fused_kernel(const float* __restrict__ x,
                      const float* __restrict__ W1,
                      const float* __restrict__ W2,
                      float* __restrict__ out,
                      long long avg_off)
{
    __shared__ float4 xs[T_STEPS];              // 16 KB
    __shared__ float  tailbuf[TAIL][2][NWARP];
    __shared__ float  sg[2][TAIL];

    const int b    = blockIdx.x >> 1;
    const int half = blockIdx.x & 1;
    const int tid  = threadIdx.x;

    // Stage inputs: half 0 needs [0,500), half 1 needs everything (warmup + store).
    const int stage_lim = half ? T_STEPS : T_HALF;
    for (int t = tid; t < stage_lim; t += NT) {
        const float* xp = x + ((size_t)t * B + b) * IN_DIM;
        xs[t] = make_float4(xp[0], xp[1], xp[2], 0.0f);
    }

    const int h = tid;
    const float w10 = W1[(size_t)h * IN_DIM + 0];
    const float w11 = W1[(size_t)h * IN_DIM + 1];
    const float w12 = W1[(size_t)h * IN_DIM + 2];
    const float w2r0 = W2[h];        // W2[0, h]
    const float w2r1 = W2[H + h];    // W2[1, h]

    __syncthreads();

    float mem = 0.0f;
    bool  p   = false;               // reset predicate = previous spike
    float s;

    if (half == 0) {
        // ---- store t in [0, 500) ----
        float* outp = out + (size_t)b * H + h;
        for (int tb = 0; tb < T_HALF; tb += CH0) {
#pragma unroll 10
            for (int t = tb; t < tb + CH0; ++t) {
                const float4 xv = xs[t];
                snn_step(xv.x, xv.y, xv.z, w10, w11, w12, mem, p, s);
                __stwt(outp, s);
                outp += B * H;
            }
            __syncthreads();   // bound warp drift
        }
        return;
    }

    // ---- half 1: silent warmup over [0, 500) — bit-identical recompute, no stores ----
#pragma unroll 10
    for (int t = 0; t < T_HALF; ++t) {
        const float4 xv = xs[t];
        snn_step(xv.x, xv.y, xv.z, w10, w11, w12, mem, p, s);
    }

    // ---- store t in [500, 990) ----
    float* outp = out + ((size_t)T_HALF * B + b) * H + h;
    for (int tb = T_HALF; tb < T_STEPS - TAIL; tb += CH1) {
#pragma unroll 7
        for (int t = tb; t < tb + CH1; ++t) {
            const float4 xv = xs[t];
            snn_step(xv.x, xv.y, xv.z, w10, w11, w12, mem, p, s);
            __stwt(outp, s);
            outp += B * H;
        }
        __syncthreads();
    }

    // ---- last 10 steps: stores + barrier-free partial recording ----
    const int lane = tid & 31;
    const int warp = tid >> 5;
#pragma unroll
    for (int ti = 0; ti < TAIL; ++ti) {
        const int t = T_STEPS - TAIL + ti;
        const float4 xv = xs[t];
        snn_step(xv.x, xv.y, xv.z, w10, w11, w12, mem, p, s);
        __stwt(outp, s);
        outp += B * H;

        float p0 = s * w2r0;
        float p1 = s * w2r1;
#pragma unroll
        for (int off = 16; off > 0; off >>= 1) {
            p0 += __shfl_down_sync(0xffffffffu, p0, off);
            p1 += __shfl_down_sync(0xffffffffu, p1, off);
        }
        if (lane == 0) { tailbuf[ti][0][warp] = p0; tailbuf[ti][1][warp] = p1; }
    }
    __syncthreads();

    if (tid < TAIL) {
        float d0 = 0.0f, d1 = 0.0f;
#pragma unroll
        for (int w = 0; w < NWARP; ++w) { d0 += tailbuf[tid][0][w]; d1 += tailbuf[tid][1][w]; }
        sg[0][tid] = 1.0f / (1.0f + expf(-d0));
        sg[1][tid] = 1.0f / (1.0f + expf(-d1));
    }
    __syncthreads();

    if (tid == 0) {
        float a0 = 0.0f, a1 = 0.0f;
#pragma unroll
        for (int ti = 0; ti < TAIL; ++ti) { a0 += sg[0][ti]; a1 += sg[1][ti]; }
        float* ao = out + avg_off + (size_t)b * OUT_DIM;
        ao[0] = a0 * 0.1f;
        ao[1] = a1 * 0.1f;
    }
}

extern "C" void kernel_launch(void* const* d_in, const int* in_sizes, int n_in,
                              void* d_out, int out_size) {
    const float* x  = (const float*)d_in[0];   // x_seq [1000, 256, 3]
    const float* W1 = (const float*)d_in[1];   // [512, 3]
    const float* W2 = (const float*)d_in[2];   // [2, 512]
    float* out = (float*)d_out;
    long long avg_off = (long long)out_size - (long long)(B * OUT_DIM);
    snn_fused_kernel<<<2 * B, NT>>>(x, W1, W2, out, avg_off);
}